// round 2
// baseline (speedup 1.0000x reference)
#include <cuda_runtime.h>

// Problem constants (fixed by the reference setup)
#define S1   32      // patches per image side (256/8)
#define LTOK 320     // tokens per patch problem: N * ip * ip = 5*64
#define NN   5
#define IP   8
#define HH   256
#define MID  2       // N//2
#define NBLK (S1*S1) // 1024

__device__ float g_mid_acc;
__device__ float g_all_acc;
__device__ float g_rec_acc;

__global__ void init_kernel() {
    g_mid_acc = 0.0f;
    g_all_acc = 0.0f;
    g_rec_acc = 0.0f;
}

__global__ void __launch_bounds__(LTOK) attn_loss_kernel(
    const float* __restrict__ inp,     // (1,5,3,256,256)
    const float* __restrict__ outp,    // (1,5,3,256,256)
    const float* __restrict__ Wq,      // (3,3)
    const float* __restrict__ Wk,      // (3,3)
    const float* __restrict__ bq,      // (3,)
    const float* __restrict__ bk,      // (3,)
    const float* __restrict__ bv,      // (3,)
    float* __restrict__ rec_out)       // d_out + 1, 3*256*256 floats
{
    __shared__ float4 k4[LTOK];
    __shared__ float4 v4[LTOK];
    __shared__ float  outS[LTOK][3];
    __shared__ float  wp[27];          // Wq[0:9] Wk[9:18] bq[18:21] bk[21:24] bv[24:27]
    __shared__ float  red[3];          // block partials: mid, all, rec

    const int t  = threadIdx.x;
    const int r  = blockIdx.x;
    const int r1 = r >> 5;             // patch row
    const int r2 = r & 31;             // patch col

    if (t < 9)       wp[t] = Wq[t];
    else if (t < 18) wp[t] = Wk[t - 9];
    else if (t < 21) wp[t] = bq[t - 18];
    else if (t < 24) wp[t] = bk[t - 21];
    else if (t < 27) wp[t] = bv[t - 24];
    if (t == 0) { red[0] = 0.f; red[1] = 0.f; red[2] = 0.f; }
    __syncthreads();

    // ---- load this thread's token (row l = t) and build q, k, v ----
    // l = n*64 + ph*8 + pw ; pixel = (r1*8+ph, r2*8+pw)
    const int n  = t >> 6;
    const int pp = t & 63;
    const int h  = r1 * IP + (pp >> 3);
    const int w  = r2 * IP + (pp & 7);
    const int base = ((n * 3) * HH + h) * HH + w;
    const float x0 = inp[base];
    const float x1 = inp[base + HH * HH];
    const float x2 = inp[base + 2 * HH * HH];

    const float inv_sqrt3 = 0.5773502691896258f;
    const float q0 = (wp[0] * x0 + wp[1] * x1 + wp[2] * x2 + wp[18]) * inv_sqrt3;
    const float q1 = (wp[3] * x0 + wp[4] * x1 + wp[5] * x2 + wp[19]) * inv_sqrt3;
    const float q2 = (wp[6] * x0 + wp[7] * x1 + wp[8] * x2 + wp[20]) * inv_sqrt3;

    const float kk0 = wp[9]  * x0 + wp[10] * x1 + wp[11] * x2 + wp[21];
    const float kk1 = wp[12] * x0 + wp[13] * x1 + wp[14] * x2 + wp[22];
    const float kk2 = wp[15] * x0 + wp[16] * x1 + wp[17] * x2 + wp[23];

    k4[t] = make_float4(kk0, kk1, kk2, 0.f);
    v4[t] = make_float4(x0 + wp[24], x1 + wp[25], x2 + wp[26], 0.f);
    __syncthreads();

    // ---- streaming softmax-attention for query t ----
    // No max subtraction: scores bounded, fp32 exp is safe; mathematically
    // identical to jax's max-subtracted softmax.
    float se = 0.f, a0 = 0.f, a1 = 0.f, a2 = 0.f;
#pragma unroll 4
    for (int m = 0; m < LTOK; m++) {
        const float4 kv = k4[m];
        const float sc = q0 * kv.x + q1 * kv.y + q2 * kv.z;
        const float e  = __expf(sc);
        const float4 vv = v4[m];
        se += e;
        a0 += e * vv.x;
        a1 += e * vv.y;
        a2 += e * vv.z;
    }
    const float inv = 1.0f / se;
    outS[t][0] = a0 * inv;
    outS[t][1] = a1 * inv;
    outS[t][2] = a2 * inv;
    __syncthreads();

    // ---- losses ----
    float lm = 0.f, la = 0.f, lr = 0.f;

    // all_loss / mid_loss: 960 elements (n,c,ph,pw), 3 per thread
#pragma unroll
    for (int i = 0; i < 3; i++) {
        const int e   = t + i * LTOK;
        const int n2  = e / 192;
        const int rem = e - n2 * 192;
        const int c   = rem >> 6;
        const int pp2 = rem & 63;
        const int h2  = r1 * IP + (pp2 >> 3);
        const int w2  = r2 * IP + (pp2 & 7);
        const float nin  = outp[((n2 * 3 + c) * HH + h2) * HH + w2];
        const float ninm = outp[((MID * 3 + c) * HH + h2) * HH + w2];
        const float al   = outS[n2 * 64 + pp2][c];
        const float da = nin - al;
        const float dm = ninm - al;
        la += da * da;
        lm += dm * dm;
    }

    // rec (mean over N) + rec_image write + rec_loss partial: 192 elements
    if (t < 192) {
        const int c   = t >> 6;
        const int pp2 = t & 63;
        const int h2  = r1 * IP + (pp2 >> 3);
        const int w2  = r2 * IP + (pp2 & 7);
        const float rec = 0.2f * (outS[pp2][c] + outS[64 + pp2][c] + outS[128 + pp2][c]
                                  + outS[192 + pp2][c] + outS[256 + pp2][c]);
        rec_out[(c * HH + h2) * HH + w2] = rec;
        const float om = outp[((MID * 3 + c) * HH + h2) * HH + w2];
        const float d  = om - rec;
        lr = d * d;
    }

    // warp reduce then block reduce
#pragma unroll
    for (int o = 16; o > 0; o >>= 1) {
        lm += __shfl_down_sync(0xffffffffu, lm, o);
        la += __shfl_down_sync(0xffffffffu, la, o);
        lr += __shfl_down_sync(0xffffffffu, lr, o);
    }
    if ((t & 31) == 0) {
        atomicAdd(&red[0], lm);
        atomicAdd(&red[1], la);
        atomicAdd(&red[2], lr);
    }
    __syncthreads();
    if (t == 0) {
        atomicAdd(&g_mid_acc, red[0] * (1.0f / 960.0f));
        atomicAdd(&g_all_acc, red[1] * (1.0f / 960.0f));
        atomicAdd(&g_rec_acc, red[2]);
    }
}

__global__ void final_kernel(const float* __restrict__ loss_diff,
                             const int* __restrict__ step,
                             const int* __restrict__ max_steps,
                             float* __restrict__ out)
{
    const float frac = 1.0f - (float)step[0] / (float)max_steps[0];
    float p = frac;
    // frac^10 exactly via repeated multiply (matches (0.9)^10 to fp32 rounding)
    float f2 = p * p;           // ^2
    float f4 = f2 * f2;         // ^4
    float f8 = f4 * f4;         // ^8
    float f10 = f8 * f2;        // ^10
    const float coeff = loss_diff[0] * f10;
    out[0] = g_mid_acc + coeff * g_all_acc + g_rec_acc * (1.0f / 196608.0f);
}

extern "C" void kernel_launch(void* const* d_in, const int* in_sizes, int n_in,
                              void* d_out, int out_size)
{
    const float* inp  = (const float*)d_in[0];
    const float* outp = (const float*)d_in[1];
    const float* Wq   = (const float*)d_in[2];
    const float* Wk   = (const float*)d_in[3];
    const float* bq   = (const float*)d_in[4];
    const float* bk   = (const float*)d_in[5];
    const float* bv   = (const float*)d_in[6];
    const float* ld   = (const float*)d_in[7];
    const int*   st   = (const int*)d_in[8];
    const int*   ms   = (const int*)d_in[9];
    float* out = (float*)d_out;

    init_kernel<<<1, 1>>>();
    attn_loss_kernel<<<NBLK, LTOK>>>(inp, outp, Wq, Wk, bq, bk, bv, out + 1);
    final_kernel<<<1, 1>>>(ld, st, ms, out);
}

// round 3
// speedup vs baseline: 1.0010x; 1.0010x over previous
#include <cuda_runtime.h>

// Problem constants (fixed by the reference setup)
#define S1   32      // patches per image side (256/8)
#define LTOK 320     // tokens per patch problem: N * ip * ip = 5*64
#define NN   5
#define IP   8
#define HH   256
#define MID  2       // N//2
#define NBLK (S1*S1) // 1024

__device__ float g_mid_acc;
__device__ float g_all_acc;
__device__ float g_rec_acc;

__global__ void init_kernel() {
    g_mid_acc = 0.0f;
    g_all_acc = 0.0f;
    g_rec_acc = 0.0f;
}

__global__ void __launch_bounds__(LTOK) attn_loss_kernel(
    const float* __restrict__ inp,     // (1,5,3,256,256)
    const float* __restrict__ outp,    // (1,5,3,256,256)
    const float* __restrict__ Wq,      // (3,3)
    const float* __restrict__ Wk,      // (3,3)
    const float* __restrict__ bq,      // (3,)
    const float* __restrict__ bk,      // (3,)
    const float* __restrict__ bv,      // (3,)
    float* __restrict__ rec_out)       // d_out + 1, 3*256*256 floats
{
    __shared__ float4 k4[LTOK];
    __shared__ float4 v4[LTOK];
    __shared__ float  outS[LTOK][3];
    __shared__ float  wp[27];          // Wq[0:9] Wk[9:18] bq[18:21] bk[21:24] bv[24:27]
    __shared__ float  red[3];          // block partials: mid, all, rec

    const int t  = threadIdx.x;
    const int r  = blockIdx.x;
    const int r1 = r >> 5;             // patch row
    const int r2 = r & 31;             // patch col

    if (t < 9)       wp[t] = Wq[t];
    else if (t < 18) wp[t] = Wk[t - 9];
    else if (t < 21) wp[t] = bq[t - 18];
    else if (t < 24) wp[t] = bk[t - 21];
    else if (t < 27) wp[t] = bv[t - 24];
    if (t == 0) { red[0] = 0.f; red[1] = 0.f; red[2] = 0.f; }
    __syncthreads();

    // ---- load this thread's token (row l = t) and build q, k, v ----
    // l = n*64 + ph*8 + pw ; pixel = (r1*8+ph, r2*8+pw)
    const int n  = t >> 6;
    const int pp = t & 63;
    const int h  = r1 * IP + (pp >> 3);
    const int w  = r2 * IP + (pp & 7);
    const int base = ((n * 3) * HH + h) * HH + w;
    const float x0 = inp[base];
    const float x1 = inp[base + HH * HH];
    const float x2 = inp[base + 2 * HH * HH];

    const float inv_sqrt3 = 0.5773502691896258f;
    const float q0 = (wp[0] * x0 + wp[1] * x1 + wp[2] * x2 + wp[18]) * inv_sqrt3;
    const float q1 = (wp[3] * x0 + wp[4] * x1 + wp[5] * x2 + wp[19]) * inv_sqrt3;
    const float q2 = (wp[6] * x0 + wp[7] * x1 + wp[8] * x2 + wp[20]) * inv_sqrt3;

    const float kk0 = wp[9]  * x0 + wp[10] * x1 + wp[11] * x2 + wp[21];
    const float kk1 = wp[12] * x0 + wp[13] * x1 + wp[14] * x2 + wp[22];
    const float kk2 = wp[15] * x0 + wp[16] * x1 + wp[17] * x2 + wp[23];

    k4[t] = make_float4(kk0, kk1, kk2, 0.f);
    v4[t] = make_float4(x0 + wp[24], x1 + wp[25], x2 + wp[26], 0.f);
    __syncthreads();

    // ---- streaming softmax-attention for query t ----
    // No max subtraction: scores bounded, fp32 exp is safe; mathematically
    // identical to jax's max-subtracted softmax.
    float se = 0.f, a0 = 0.f, a1 = 0.f, a2 = 0.f;
#pragma unroll 4
    for (int m = 0; m < LTOK; m++) {
        const float4 kv = k4[m];
        const float sc = q0 * kv.x + q1 * kv.y + q2 * kv.z;
        const float e  = __expf(sc);
        const float4 vv = v4[m];
        se += e;
        a0 += e * vv.x;
        a1 += e * vv.y;
        a2 += e * vv.z;
    }
    const float inv = 1.0f / se;
    outS[t][0] = a0 * inv;
    outS[t][1] = a1 * inv;
    outS[t][2] = a2 * inv;
    __syncthreads();

    // ---- losses ----
    float lm = 0.f, la = 0.f, lr = 0.f;

    // all_loss / mid_loss: 960 elements (n,c,ph,pw), 3 per thread
#pragma unroll
    for (int i = 0; i < 3; i++) {
        const int e   = t + i * LTOK;
        const int n2  = e / 192;
        const int rem = e - n2 * 192;
        const int c   = rem >> 6;
        const int pp2 = rem & 63;
        const int h2  = r1 * IP + (pp2 >> 3);
        const int w2  = r2 * IP + (pp2 & 7);
        const float nin  = outp[((n2 * 3 + c) * HH + h2) * HH + w2];
        const float ninm = outp[((MID * 3 + c) * HH + h2) * HH + w2];
        const float al   = outS[n2 * 64 + pp2][c];
        const float da = nin - al;
        const float dm = ninm - al;
        la += da * da;
        lm += dm * dm;
    }

    // rec (mean over N) + rec_image write + rec_loss partial: 192 elements
    if (t < 192) {
        const int c   = t >> 6;
        const int pp2 = t & 63;
        const int h2  = r1 * IP + (pp2 >> 3);
        const int w2  = r2 * IP + (pp2 & 7);
        const float rec = 0.2f * (outS[pp2][c] + outS[64 + pp2][c] + outS[128 + pp2][c]
                                  + outS[192 + pp2][c] + outS[256 + pp2][c]);
        rec_out[(c * HH + h2) * HH + w2] = rec;
        const float om = outp[((MID * 3 + c) * HH + h2) * HH + w2];
        const float d  = om - rec;
        lr = d * d;
    }

    // warp reduce then block reduce
#pragma unroll
    for (int o = 16; o > 0; o >>= 1) {
        lm += __shfl_down_sync(0xffffffffu, lm, o);
        la += __shfl_down_sync(0xffffffffu, la, o);
        lr += __shfl_down_sync(0xffffffffu, lr, o);
    }
    if ((t & 31) == 0) {
        atomicAdd(&red[0], lm);
        atomicAdd(&red[1], la);
        atomicAdd(&red[2], lr);
    }
    __syncthreads();
    if (t == 0) {
        atomicAdd(&g_mid_acc, red[0] * (1.0f / 960.0f));
        atomicAdd(&g_all_acc, red[1] * (1.0f / 960.0f));
        atomicAdd(&g_rec_acc, red[2]);
    }
}

__global__ void final_kernel(const float* __restrict__ loss_diff,
                             const int* __restrict__ step,
                             const int* __restrict__ max_steps,
                             float* __restrict__ out)
{
    const float frac = 1.0f - (float)step[0] / (float)max_steps[0];
    float p = frac;
    // frac^10 exactly via repeated multiply (matches (0.9)^10 to fp32 rounding)
    float f2 = p * p;           // ^2
    float f4 = f2 * f2;         // ^4
    float f8 = f4 * f4;         // ^8
    float f10 = f8 * f2;        // ^10
    const float coeff = loss_diff[0] * f10;
    out[0] = g_mid_acc + coeff * g_all_acc + g_rec_acc * (1.0f / 196608.0f);
}

extern "C" void kernel_launch(void* const* d_in, const int* in_sizes, int n_in,
                              void* d_out, int out_size)
{
    const float* inp  = (const float*)d_in[0];
    const float* outp = (const float*)d_in[1];
    const float* Wq   = (const float*)d_in[2];
    const float* Wk   = (const float*)d_in[3];
    const float* bq   = (const float*)d_in[4];
    const float* bk   = (const float*)d_in[5];
    const float* bv   = (const float*)d_in[6];
    const float* ld   = (const float*)d_in[7];
    const int*   st   = (const int*)d_in[8];
    const int*   ms   = (const int*)d_in[9];
    float* out = (float*)d_out;

    init_kernel<<<1, 1>>>();
    attn_loss_kernel<<<NBLK, LTOK>>>(inp, outp, Wq, Wk, bq, bk, bv, out + 1);
    final_kernel<<<1, 1>>>(ld, st, ms, out);
}